// round 4
// baseline (speedup 1.0000x reference)
#include <cuda_runtime.h>
#include <math.h>
#include <stdint.h>

// ---------------- problem constants ----------------
constexpr int Bb   = 32;
constexpr int Nn   = 196;
constexpr int Cc   = 768;
constexpr int Hh   = 12;
constexpr int Ll   = 4;
constexpr int DFF  = 3072;
constexpr int HD   = Cc / Hh;          // 64
constexpr int ROWS = Bb * Nn;          // 6272
constexpr int NCAT = 2 * Nn;           // 392

// weight sizes per stream
constexpr int W_QKV = Cc * 3 * Cc;     // 1769472
constexpr int W_PRJ = Cc * Cc;         // 589824
constexpr int W_FC1 = Cc * DFF;        // 2359296
constexpr int W_FC2 = DFF * Cc;        // 2359296
constexpr int W_ALL = W_QKV + W_PRJ + W_FC1 + W_FC2;

// ---------------- scratch (static device memory; no allocation) ----------------
__device__ float g_fused[Bb * Ll * Cc];
__device__ float g_h   [2 * ROWS * Cc];
__device__ float g_qkv [2 * ROWS * 3 * Cc];
__device__ float g_o   [2 * ROWS * Cc];
__device__ float g_mlp [2 * ROWS * DFF];
__device__ float g_w   [2 * W_ALL];              // tf32-rounded weights

__device__ __forceinline__ float f2tf32(float x) {
    uint32_t r;
    asm("cvt.rna.tf32.f32 %0, %1;" : "=r"(r) : "f"(x));
    return __uint_as_float(r);
}

// ============================================================================
// round weights to tf32 (rna), float4-vectorized
// ============================================================================
__global__ void round_w_kernel(const float* __restrict__ in, float* __restrict__ out, int n4)
{
    int i = blockIdx.x * blockDim.x + threadIdx.x;
    if (i < n4) {
        float4 v = ((const float4*)in)[i];
        v.x = f2tf32(v.x); v.y = f2tf32(v.y); v.z = f2tf32(v.z); v.w = f2tf32(v.w);
        ((float4*)out)[i] = v;
    }
}

// ============================================================================
// Kernel 1: fused latents = sdpa(latents, concat(x,y), concat(x,y), C^-0.5)
// ============================================================================
__global__ void fuse_latents_kernel(const float* __restrict__ x,
                                    const float* __restrict__ y,
                                    const float* __restrict__ lat,
                                    float* __restrict__ fused)
{
    const int b = blockIdx.x / Ll;
    const int l = blockIdx.x % Ll;
    const int tid = threadIdx.x, lane = tid & 31, w = tid >> 5;

    __shared__ float s[NCAT];
    __shared__ float red[64];

    const float* latrow = lat + l * Cc;
    const float scale = 0.03608439182435161f;  // 1/sqrt(768)

    for (int n = w; n < NCAT; n += 8) {
        const float* row = (n < Nn) ? x + (size_t)(b * Nn + n) * Cc
                                    : y + (size_t)(b * Nn + (n - Nn)) * Cc;
        float acc = 0.f;
        for (int c = lane; c < Cc; c += 32) acc += latrow[c] * row[c];
        #pragma unroll
        for (int o = 16; o; o >>= 1) acc += __shfl_xor_sync(0xffffffffu, acc, o);
        if (lane == 0) s[n] = acc * scale;
    }
    __syncthreads();

    float mx = -INFINITY;
    for (int n = tid; n < NCAT; n += 256) mx = fmaxf(mx, s[n]);
    #pragma unroll
    for (int o = 16; o; o >>= 1) mx = fmaxf(mx, __shfl_xor_sync(0xffffffffu, mx, o));
    if (lane == 0) red[w] = mx;
    __syncthreads();
    mx = red[0];
    #pragma unroll
    for (int i = 1; i < 8; i++) mx = fmaxf(mx, red[i]);
    __syncthreads();

    float sum = 0.f;
    for (int n = tid; n < NCAT; n += 256) {
        float e = __expf(s[n] - mx);
        s[n] = e;
        sum += e;
    }
    #pragma unroll
    for (int o = 16; o; o >>= 1) sum += __shfl_xor_sync(0xffffffffu, sum, o);
    if (lane == 0) red[8 + w] = sum;
    __syncthreads();
    sum = 0.f;
    #pragma unroll
    for (int i = 0; i < 8; i++) sum += red[8 + i];
    const float inv = 1.f / sum;
    for (int n = tid; n < NCAT; n += 256) s[n] *= inv;
    __syncthreads();

    for (int c = tid; c < Cc; c += 256) {
        float acc = 0.f;
        const float* xp = x + (size_t)b * Nn * Cc + c;
        for (int n = 0; n < Nn; n++) acc += s[n] * xp[(size_t)n * Cc];
        const float* yp = y + (size_t)b * Nn * Cc + c;
        for (int n = 0; n < Nn; n++) acc += s[Nn + n] * yp[(size_t)n * Cc];
        fused[(size_t)(b * Ll + l) * Cc + c] = acc;
    }
}

// ============================================================================
// Kernel 2: out = in + scale * sdpa(in, fused, fused, C^-0.5)
// ============================================================================
__global__ void cross_attend_kernel(const float* __restrict__ x,
                                    const float* __restrict__ y,
                                    const float* __restrict__ fused,
                                    const float* __restrict__ scale_a,
                                    const float* __restrict__ scale_v,
                                    float* __restrict__ outx,
                                    float* __restrict__ outy)
{
    const int row = blockIdx.x;
    const int b = row / Nn;
    const int tid = threadIdx.x;

    const float* in;
    float* out;
    float sc;
    if (blockIdx.y == 0) { in = x + (size_t)row * Cc; out = outx + (size_t)row * Cc; sc = *scale_a; }
    else                 { in = y + (size_t)row * Cc; out = outy + (size_t)row * Cc; sc = *scale_v; }

    const float* f = fused + (size_t)b * Ll * Cc;

    __shared__ float red[256];
    __shared__ float w4[Ll];

    float p0 = 0.f, p1 = 0.f, p2 = 0.f, p3 = 0.f;
    for (int c = tid; c < Cc; c += 256) {
        float v = in[c];
        p0 += v * f[c];
        p1 += v * f[Cc + c];
        p2 += v * f[2 * Cc + c];
        p3 += v * f[3 * Cc + c];
    }
    float ps[4] = {p0, p1, p2, p3};
    #pragma unroll
    for (int l = 0; l < Ll; l++) {
        red[tid] = ps[l];
        __syncthreads();
        for (int st = 128; st; st >>= 1) {
            if (tid < st) red[tid] += red[tid + st];
            __syncthreads();
        }
        if (tid == 0) w4[l] = red[0] * 0.03608439182435161f;
        __syncthreads();
    }
    if (tid == 0) {
        float mx = fmaxf(fmaxf(w4[0], w4[1]), fmaxf(w4[2], w4[3]));
        float e0 = __expf(w4[0] - mx), e1 = __expf(w4[1] - mx);
        float e2 = __expf(w4[2] - mx), e3 = __expf(w4[3] - mx);
        float inv = 1.f / (e0 + e1 + e2 + e3);
        w4[0] = e0 * inv; w4[1] = e1 * inv; w4[2] = e2 * inv; w4[3] = e3 * inv;
    }
    __syncthreads();

    const float a0 = w4[0], a1 = w4[1], a2 = w4[2], a3 = w4[3];
    for (int c = tid; c < Cc; c += 256) {
        float r = a0 * f[c] + a1 * f[Cc + c] + a2 * f[2 * Cc + c] + a3 * f[3 * Cc + c];
        out[c] = in[c] + sc * r;
    }
}

// ============================================================================
// LayerNorm (batched over 2 streams); output rounded to tf32 (feeds GEMM A)
// ============================================================================
__global__ void ln_kernel(const float* __restrict__ inb,
                          const float* __restrict__ g0, const float* __restrict__ b0,
                          const float* __restrict__ g1, const float* __restrict__ b1,
                          float* __restrict__ outb)
{
    const int z = blockIdx.y;
    const int row = blockIdx.x;
    const int tid = threadIdx.x;
    const float* g   = z ? g1 : g0;
    const float* bta = z ? b1 : b0;
    const float* ip = inb  + ((size_t)z * ROWS + row) * Cc;
    float*       op = outb + ((size_t)z * ROWS + row) * Cc;

    __shared__ float red[256];
    __shared__ float s_mean, s_rstd;

    float v0 = ip[tid], v1 = ip[tid + 256], v2 = ip[tid + 512];
    float sum = v0 + v1 + v2;
    red[tid] = sum;
    __syncthreads();
    for (int st = 128; st; st >>= 1) { if (tid < st) red[tid] += red[tid + st]; __syncthreads(); }
    if (tid == 0) s_mean = red[0] * (1.f / Cc);
    __syncthreads();
    const float mean = s_mean;

    float d0 = v0 - mean, d1 = v1 - mean, d2 = v2 - mean;
    red[tid] = d0 * d0 + d1 * d1 + d2 * d2;
    __syncthreads();
    for (int st = 128; st; st >>= 1) { if (tid < st) red[tid] += red[tid + st]; __syncthreads(); }
    if (tid == 0) s_rstd = rsqrtf(red[0] * (1.f / Cc) + 1e-6f);
    __syncthreads();
    const float rstd = s_rstd;

    op[tid]       = f2tf32(d0 * rstd * g[tid]       + bta[tid]);
    op[tid + 256] = f2tf32(d1 * rstd * g[tid + 256] + bta[tid + 256]);
    op[tid + 512] = f2tf32(d2 * rstd * g[tid + 512] + bta[tid + 512]);
}

// ============================================================================
// TF32 tensor-core GEMM, 3-stage cp.async pipeline, batched over 2 streams.
// C_z[M,N] = A_z[M,K] @ W_z[K,N] + bias_z (+gelu | +residual_z)
// 128x128x16 tile, 256 threads (8 warps 2x4), warp tile 64x32, m16n8k8.tf32.
// A smem m-major [128][20]; B k-major [16][136]. Inputs pre-rounded to tf32.
// ============================================================================
constexpr int LDA = 20;
constexpr int LDB = 136;
constexpr int STAGES = 3;
constexpr int A_STG = 128 * LDA;                 // floats per A stage
constexpr int B_STG = 16 * LDB;                  // floats per B stage
constexpr int GEMM_SMEM = (STAGES * (A_STG + B_STG)) * 4;   // 56832 B

__device__ __forceinline__ void cp_async16(uint32_t s, const void* g) {
    asm volatile("cp.async.ca.shared.global [%0], [%1], 16;" :: "r"(s), "l"(g));
}
__device__ __forceinline__ void cp_commit() {
    asm volatile("cp.async.commit_group;");
}
template<int N>
__device__ __forceinline__ void cp_wait() {
    asm volatile("cp.async.wait_group %0;" :: "n"(N));
}

template<int EPI>
__global__ __launch_bounds__(256, 2)
void tf32_gemm_kernel(const float* __restrict__ Abase, size_t strideA,
                      const float* __restrict__ W0, const float* __restrict__ W1,
                      const float* __restrict__ bias0, const float* __restrict__ bias1,
                      const float* __restrict__ resbase,
                      float* __restrict__ Cbase, size_t strideC,
                      int M, int N, int K)
{
    extern __shared__ float smem[];
    float* As = smem;
    float* Bs = smem + STAGES * A_STG;

    const int z = blockIdx.z;
    const float* A    = Abase + (size_t)z * strideA;
    const float* W    = z ? W1 : W0;
    const float* bias = z ? bias1 : bias0;
    const float* res  = (EPI == 2) ? resbase + (size_t)z * strideC : nullptr;
    float*       C    = Cbase + (size_t)z * strideC;

    const int tid  = threadIdx.x;
    const int lane = tid & 31;
    const int w    = tid >> 5;
    const int wm   = w >> 2;
    const int wn   = w & 3;
    const int gid  = lane >> 2;
    const int tig  = lane & 3;

    const int bm = blockIdx.y * 128;
    const int bn = blockIdx.x * 128;

    float acc[4][4][4];
    #pragma unroll
    for (int i = 0; i < 4; i++)
        #pragma unroll
        for (int j = 0; j < 4; j++)
            #pragma unroll
            for (int q = 0; q < 4; q++) acc[i][j][q] = 0.f;

    const int ar = tid >> 2;
    const int ac = (tid & 3) * 4;
    const int bkr = tid >> 5;
    const int bc = (tid & 31) * 4;

    const float* Ap = A + (size_t)(bm + ar) * K + ac;
    const float* Bp = W + (size_t)bkr * N + bn + bc;

    const uint32_t sA = (uint32_t)__cvta_generic_to_shared(&As[ar * LDA + ac]);
    const uint32_t sB = (uint32_t)__cvta_generic_to_shared(&Bs[bkr * LDB + bc]);

    const int KT = K / 16;

    auto load_tile = [&](int kt, int stg) {
        const float* a = Ap + kt * 16;
        const float* b = Bp + (size_t)kt * 16 * N;
        const uint32_t sa = sA + stg * (A_STG * 4);
        const uint32_t sb = sB + stg * (B_STG * 4);
        cp_async16(sa, a);
        cp_async16(sa + 64 * LDA * 4, a + (size_t)64 * K);
        cp_async16(sb, b);
        cp_async16(sb + 8 * LDB * 4, b + (size_t)8 * N);
        cp_commit();
    };

    // prologue: two tiles in flight
    load_tile(0, 0);
    load_tile(1, 1);
    cp_wait<1>();                 // tile 0 arrived
    __syncthreads();

    const int abase = (wm * 64 + gid) * LDA + tig;
    const int bbase = tig * LDB + wn * 32 + gid;

    int buf = 0;
    for (int kt = 0; kt < KT; kt++) {
        if (kt + 2 < KT) {
            int s2 = buf + 2; if (s2 >= STAGES) s2 -= STAGES;
            load_tile(kt + 2, s2);
        }

        const float* Ab = As + buf * A_STG;
        const float* Bb = Bs + buf * B_STG;
        #pragma unroll
        for (int ks = 0; ks < 2; ks++) {
            uint32_t af[4][4];
            #pragma unroll
            for (int i = 0; i < 4; i++) {
                const int a0 = abase + i * 16 * LDA + ks * 8;
                af[i][0] = __float_as_uint(Ab[a0]);
                af[i][1] = __float_as_uint(Ab[a0 + 8 * LDA]);
                af[i][2] = __float_as_uint(Ab[a0 + 4]);
                af[i][3] = __float_as_uint(Ab[a0 + 8 * LDA + 4]);
            }
            uint32_t bf[4][2];
            #pragma unroll
            for (int j = 0; j < 4; j++) {
                const int b0 = bbase + ks * 8 * LDB + j * 8;
                bf[j][0] = __float_as_uint(Bb[b0]);
                bf[j][1] = __float_as_uint(Bb[b0 + 4 * LDB]);
            }
            #pragma unroll
            for (int i = 0; i < 4; i++)
                #pragma unroll
                for (int j = 0; j < 4; j++) {
                    asm volatile(
                        "mma.sync.aligned.m16n8k8.row.col.f32.tf32.tf32.f32 "
                        "{%0,%1,%2,%3}, {%4,%5,%6,%7}, {%8,%9}, {%0,%1,%2,%3};"
                        : "+f"(acc[i][j][0]), "+f"(acc[i][j][1]),
                          "+f"(acc[i][j][2]), "+f"(acc[i][j][3])
                        : "r"(af[i][0]), "r"(af[i][1]), "r"(af[i][2]), "r"(af[i][3]),
                          "r"(bf[j][0]), "r"(bf[j][1]));
                }
        }

        if (kt + 1 < KT) {
            cp_wait<1>();          // tile kt+1 arrived
            __syncthreads();
            buf = (buf + 1 < STAGES) ? buf + 1 : 0;
        }
    }

    // ---- epilogue ----
    #pragma unroll
    for (int i = 0; i < 4; i++) {
        const int r0 = bm + wm * 64 + i * 16 + gid;
        #pragma unroll
        for (int j = 0; j < 4; j++) {
            const int c = bn + wn * 32 + j * 8 + tig * 2;
            const float b0 = bias[c], b1 = bias[c + 1];

            float v0 = acc[i][j][0] + b0;
            float v1 = acc[i][j][1] + b1;
            float v2 = acc[i][j][2] + b0;
            float v3 = acc[i][j][3] + b1;
            if (EPI == 1) {   // gelu, rounded to tf32 (feeds fc2 GEMM A)
                v0 = f2tf32(v0 * 0.5f * (1.f + erff(v0 * 0.70710678118654752f)));
                v1 = f2tf32(v1 * 0.5f * (1.f + erff(v1 * 0.70710678118654752f)));
                v2 = f2tf32(v2 * 0.5f * (1.f + erff(v2 * 0.70710678118654752f)));
                v3 = f2tf32(v3 * 0.5f * (1.f + erff(v3 * 0.70710678118654752f)));
            }
            if (EPI == 2) {
                const float* r = res + (size_t)r0 * N + c;
                v0 += r[0]; v1 += r[1];
                const float* r2 = res + (size_t)(r0 + 8) * N + c;
                v2 += r2[0]; v3 += r2[1];
            }
            *(float2*)&C[(size_t)r0 * N + c]       = make_float2(v0, v1);
            *(float2*)&C[(size_t)(r0 + 8) * N + c] = make_float2(v2, v3);
        }
    }
}

// ============================================================================
// Attention: one block per (b, head); batched over streams via blockIdx.y
// output rounded to tf32 (feeds proj GEMM A)
// ============================================================================
constexpr int KVSTRIDE = HD + 1;                                    // 65
constexpr int ATTN_SMEM = (2 * Nn * KVSTRIDE + 8 * Nn + 8 * HD) * 4; // 110240 B

__global__ void attn_kernel(const float* __restrict__ qkvb_, float* __restrict__ ob_)
{
    extern __shared__ float sm[];
    float* Ks = sm;
    float* Vs = Ks + Nn * KVSTRIDE;
    float* S  = Vs + Nn * KVSTRIDE;
    float* Qs = S + 8 * Nn;

    const int z = blockIdx.y;
    const int bh = blockIdx.x;
    const int b = bh / Hh, hh = bh % Hh;
    const int tid = threadIdx.x, lane = tid & 31, w = tid >> 5;

    const float* qkvb = qkvb_ + (size_t)z * ROWS * 3 * Cc + (size_t)b * Nn * (3 * Cc);
    float* o = ob_ + (size_t)z * ROWS * Cc;

    for (int idx = tid; idx < Nn * HD; idx += 256) {
        const int n = idx >> 6, d = idx & 63;
        const float* rp = qkvb + (size_t)n * (3 * Cc) + hh * HD + d;
        Ks[n * KVSTRIDE + d] = rp[Cc];
        Vs[n * KVSTRIDE + d] = rp[2 * Cc];
    }
    __syncthreads();

    float* Sw = S + w * Nn;
    float* Qw = Qs + w * HD;

    for (int r = w; r < Nn; r += 8) {
        const float* qp = qkvb + (size_t)r * (3 * Cc) + hh * HD;
        Qw[lane] = qp[lane];
        Qw[lane + 32] = qp[lane + 32];
        __syncwarp();

        float mx = -INFINITY;
        for (int k = lane; k < Nn; k += 32) {
            float acc = 0.f;
            #pragma unroll
            for (int d = 0; d < HD; d++) acc = fmaf(Qw[d], Ks[k * KVSTRIDE + d], acc);
            acc *= 0.125f;
            Sw[k] = acc;
            mx = fmaxf(mx, acc);
        }
        #pragma unroll
        for (int off = 16; off; off >>= 1) mx = fmaxf(mx, __shfl_xor_sync(0xffffffffu, mx, off));

        float sum = 0.f;
        for (int k = lane; k < Nn; k += 32) {
            float e = __expf(Sw[k] - mx);
            Sw[k] = e;
            sum += e;
        }
        #pragma unroll
        for (int off = 16; off; off >>= 1) sum += __shfl_xor_sync(0xffffffffu, sum, off);
        const float inv = 1.f / sum;
        __syncwarp();

        float a0 = 0.f, a1 = 0.f;
        for (int k = 0; k < Nn; k++) {
            const float p = Sw[k];
            a0 = fmaf(p, Vs[k * KVSTRIDE + lane], a0);
            a1 = fmaf(p, Vs[k * KVSTRIDE + lane + 32], a1);
        }
        float* op = o + (size_t)(b * Nn + r) * Cc + hh * HD;
        op[lane] = f2tf32(a0 * inv);
        op[lane + 32] = f2tf32(a1 * inv);
        __syncwarp();
    }
}

// ============================================================================
// host launcher
// ============================================================================
extern "C" void kernel_launch(void* const* d_in, const int* in_sizes, int n_in,
                              void* d_out, int out_size)
{
    const float* x        = (const float*)d_in[0];
    const float* y        = (const float*)d_in[1];
    const float* latents  = (const float*)d_in[2];
    const float* scale_a  = (const float*)d_in[3];
    const float* scale_v  = (const float*)d_in[4];

    const float* sp[12];
    const float* rp[12];
    for (int i = 0; i < 12; i++) { sp[i] = (const float*)d_in[5 + i]; rp[i] = (const float*)d_in[17 + i]; }

    float* outx = (float*)d_out;

    float *fused, *hbuf, *qkvbuf, *obuf, *mlpbuf, *wbuf;
    cudaGetSymbolAddress((void**)&fused,  g_fused);
    cudaGetSymbolAddress((void**)&hbuf,   g_h);
    cudaGetSymbolAddress((void**)&qkvbuf, g_qkv);
    cudaGetSymbolAddress((void**)&obuf,   g_o);
    cudaGetSymbolAddress((void**)&mlpbuf, g_mlp);
    cudaGetSymbolAddress((void**)&wbuf,   g_w);

    cudaFuncSetAttribute(attn_kernel, cudaFuncAttributeMaxDynamicSharedMemorySize, ATTN_SMEM);
    cudaFuncSetAttribute(tf32_gemm_kernel<0>, cudaFuncAttributeMaxDynamicSharedMemorySize, GEMM_SMEM);
    cudaFuncSetAttribute(tf32_gemm_kernel<1>, cudaFuncAttributeMaxDynamicSharedMemorySize, GEMM_SMEM);
    cudaFuncSetAttribute(tf32_gemm_kernel<2>, cudaFuncAttributeMaxDynamicSharedMemorySize, GEMM_SMEM);

    const size_t sC   = (size_t)ROWS * Cc;
    const size_t sQKV = (size_t)ROWS * 3 * Cc;
    const size_t sMLP = (size_t)ROWS * DFF;

    // rounded weight layout per stream: [qkv | proj | fc1 | fc2]
    float* wq[2]; float* wp[2]; float* w1[2]; float* w2[2];
    for (int s = 0; s < 2; s++) {
        float* base = wbuf + (size_t)s * W_ALL;
        wq[s] = base;
        wp[s] = base + W_QKV;
        w1[s] = base + W_QKV + W_PRJ;
        w2[s] = base + W_QKV + W_PRJ + W_FC1;
    }
    for (int s = 0; s < 2; s++) {
        const float** P = (s == 0) ? sp : rp;
        round_w_kernel<<<(W_QKV / 4 + 255) / 256, 256>>>(P[2],  wq[s], W_QKV / 4);
        round_w_kernel<<<(W_PRJ / 4 + 255) / 256, 256>>>(P[4],  wp[s], W_PRJ / 4);
        round_w_kernel<<<(W_FC1 / 4 + 255) / 256, 256>>>(P[8],  w1[s], W_FC1 / 4);
        round_w_kernel<<<(W_FC2 / 4 + 255) / 256, 256>>>(P[10], w2[s], W_FC2 / 4);
    }

    // --- latent bottleneck fusion ---
    fuse_latents_kernel<<<Bb * Ll, 256>>>(x, y, latents, fused);
    cross_attend_kernel<<<dim3(ROWS, 2), 256>>>(x, y, fused, scale_a, scale_v,
                                                outx, outx + sC);

    // --- ViT blocks, both streams batched over blockIdx.z ---
    ln_kernel<<<dim3(ROWS, 2), 256>>>(outx, sp[0], sp[1], rp[0], rp[1], hbuf);
    tf32_gemm_kernel<0><<<dim3(3 * Cc / 128, ROWS / 128, 2), 256, GEMM_SMEM>>>(
        hbuf, sC, wq[0], wq[1], sp[3], rp[3], nullptr, qkvbuf, sQKV,
        ROWS, 3 * Cc, Cc);

    attn_kernel<<<dim3(Bb * Hh, 2), 256, ATTN_SMEM>>>(qkvbuf, obuf);

    tf32_gemm_kernel<2><<<dim3(Cc / 128, ROWS / 128, 2), 256, GEMM_SMEM>>>(
        obuf, sC, wp[0], wp[1], sp[5], rp[5], outx, outx, sC,
        ROWS, Cc, Cc);

    ln_kernel<<<dim3(ROWS, 2), 256>>>(outx, sp[6], sp[7], rp[6], rp[7], hbuf);
    tf32_gemm_kernel<1><<<dim3(DFF / 128, ROWS / 128, 2), 256, GEMM_SMEM>>>(
        hbuf, sC, w1[0], w1[1], sp[9], rp[9], nullptr, mlpbuf, sMLP,
        ROWS, DFF, Cc);
    tf32_gemm_kernel<2><<<dim3(Cc / 128, ROWS / 128, 2), 256, GEMM_SMEM>>>(
        mlpbuf, sMLP, w2[0], w2[1], sp[11], rp[11], outx, outx, sC,
        ROWS, Cc, DFF);
}